// round 16
// baseline (speedup 1.0000x reference)
#include <cuda_runtime.h>
#include <cstdint>

#define BB   2
#define SS   2048
#define DD   1024
#define HH   16
#define DKV  64
#define BH   (BB*HH)
#define NC   (SS/64)      // 32 j-chunks

static const size_t OUT_OFF = (size_t)BB * SS * DD;

__device__ float g_q [(size_t)BH * SS * DKV];          // [bh][s][64] raw fp32
__device__ float g_k [(size_t)BH * SS * DKV];          // [bh][s][64] tf32 bits, d-pair-permuted
__device__ float g_vT[(size_t)BH * DKV * SS];          // [bh][d][s]  tf32 bits, s-pair-permuted
__device__ float g_ao[(size_t)BB * SS * HH * DKV];     // [b][s][h*64+d] raw fp32
__device__ float g_invL[(size_t)BH * SS];              // per-row 1/L
__device__ float g_wT [(size_t)4 * DD * DD];           // [z][n][k] tf32 bits, k-pair-permuted
__device__ float g_in [(size_t)3 * BB * SS * DD];      // [z] slab-frag-major tf32 bits
__device__ uint32_t g_mbits[(size_t)BB * SS * (SS/32)];// packed mask bits

// ---------------------------------------------------------------------------
__device__ __forceinline__ uint32_t f2tf32(float x) {
    uint32_t u;
    asm("cvt.rna.tf32.f32 %0, %1;" : "=r"(u) : "f"(x));
    return u;
}
__device__ __forceinline__ void mma8(float c[4], const uint32_t a[4], const uint32_t b[2]) {
    asm volatile(
        "mma.sync.aligned.m16n8k8.row.col.f32.tf32.tf32.f32 "
        "{%0,%1,%2,%3}, {%4,%5,%6,%7}, {%8,%9}, {%0,%1,%2,%3};\n"
        : "+f"(c[0]), "+f"(c[1]), "+f"(c[2]), "+f"(c[3])
        : "r"(a[0]), "r"(a[1]), "r"(a[2]), "r"(a[3]), "r"(b[0]), "r"(b[1]));
}
__device__ __forceinline__ void cpa16(uint32_t dst, const void* src) {
    asm volatile("cp.async.cg.shared.global [%0], [%1], 16;\n" :: "r"(dst), "l"(src));
}
__device__ __forceinline__ void cp_commit() { asm volatile("cp.async.commit_group;\n"); }
template<int N> __device__ __forceinline__ void cp_wait() {
    asm volatile("cp.async.wait_group %0;\n" :: "n"(N));
}
__device__ __forceinline__ uint32_t saddr(const void* p) {
    return (uint32_t)__cvta_generic_to_shared(p);
}
__device__ __forceinline__ void stcs2(float* p, float x, float y) {
    asm volatile("st.global.cs.v2.f32 [%0], {%1, %2};\n" :: "l"(p), "f"(x), "f"(y) : "memory");
}

// pair permutation within an 8-group: logical k=t and k=t+4 become adjacent.
__device__ __forceinline__ int kperm(int l) { return 2 * (l & 3) + (l >> 2); }

// 2^t on fma/alu pipes (no MUFU). Degree-4 poly, max rel err ~4e-5.
__device__ __forceinline__ float exp2_fast(float t) {
    float kf = t + 12582912.0f;
    int   n  = __float_as_int(kf) - 0x4B400000;
    float r  = t - (kf - 12582912.0f);
    float p  = 0.0096181291f;
    p = fmaf(p, r, 0.0555041087f);
    p = fmaf(p, r, 0.2402265070f);
    p = fmaf(p, r, 0.6931471806f);
    p = fmaf(p, r, 1.0f);
    return p * __int_as_float((n + 127) << 23);
}

// Fragment-major A index, K=64 tiles (fused_attn Q/P): kk in [0,8)
__device__ __forceinline__ int frag_idx(int mblk2, int kk, int g, int tp, int elem) {
    return ((((mblk2 * 8 + kk) * 8) + g) * 4 + tp) * 4 + elem;
}
// Fragment-major A index, BK=32 slabs (projection A): kk in [0,4)
__device__ __forceinline__ int frag_idx4(int mblk2, int kk, int g, int tp, int elem) {
    return ((((mblk2 * 4 + kk) * 8) + g) * 4 + tp) * 4 + elem;
}

// A: frag-major tf32 bits (K=64). B: [64 rows][72] pair-permuted tf32 bits.
__device__ __forceinline__ void mma_frag_pair(
    const float* __restrict__ Af, const float* __restrict__ Bs,
    float acc[2][4][4], int wm, int wn, int g, int t)
{
    int tp = t ^ ((g >> 1) & 3);
    #pragma unroll
    for (int kk = 0; kk < 8; kk++) {
        uint32_t a[2][4];
        #pragma unroll
        for (int mf = 0; mf < 2; mf++) {
            float4 av = *(const float4*)(Af + frag_idx(wm * 2 + mf, kk, g, tp, 0));
            a[mf][0] = __float_as_uint(av.x);
            a[mf][1] = __float_as_uint(av.y);
            a[mf][2] = __float_as_uint(av.z);
            a[mf][3] = __float_as_uint(av.w);
        }
        #pragma unroll
        for (int nf = 0; nf < 4; nf++) {
            float2 bv = *(const float2*)(Bs + (wn * 32 + nf * 8 + g) * 72 + kk * 8 + 2 * t);
            uint32_t bb[2] = {__float_as_uint(bv.x), __float_as_uint(bv.y)};
            #pragma unroll
            for (int mf = 0; mf < 2; mf++)
                mma8(acc[mf][nf], a[mf], bb);
        }
    }
}

// ---------------------------------------------------------------------------
// prep kernels
// ---------------------------------------------------------------------------
__global__ __launch_bounds__(256) void prep_w(
    const float* __restrict__ Wq, const float* __restrict__ Wk,
    const float* __restrict__ Wv, const float* __restrict__ Wo)
{
    __shared__ float tl[32][33];
    int z = blockIdx.z;
    const float* W = (z == 0) ? Wq : (z == 1) ? Wk : (z == 2) ? Wv : Wo;
    float* out = g_wT + (size_t)z * DD * DD;
    int n0 = blockIdx.x * 32, k0 = blockIdx.y * 32;
    int tx = threadIdx.x & 31, ty = threadIdx.x >> 5;   // ty 0..7
    #pragma unroll
    for (int i = 0; i < 4; i++)
        tl[ty + i * 8][tx] = W[(size_t)(k0 + ty + i * 8) * DD + n0 + tx];
    __syncthreads();
    #pragma unroll
    for (int i = 0; i < 4; i++) {
        int n = n0 + ty + i * 8;
        int k = k0 + tx;
        out[(size_t)n * DD + (k & ~7) + kperm(k & 7)]
            = __uint_as_float(f2tf32(tl[tx][ty + i * 8]));
    }
}

// Convert the 3 activation inputs into slab-frag-major tf32 layout.
__global__ __launch_bounds__(256) void prep_in(
    const float* __restrict__ q, const float* __restrict__ k,
    const float* __restrict__ v)
{
    int z = blockIdx.z;
    const float* in = (z == 0) ? q : (z == 1) ? k : v;
    float* out = g_in + (size_t)z * BB * SS * DD;
    int f4 = blockIdx.x * 256 + threadIdx.x;      // 0 .. 1,048,575
    int f4idx = f4 & 1023;
    int slab  = (f4 >> 10) & 31;
    int mtile = f4 >> 15;
    int tp = f4idx & 3, g = (f4idx >> 2) & 7;
    int kk = (f4idx >> 5) & 3, mblk2 = f4idx >> 7;
    int t = tp ^ ((g >> 1) & 3);
    int row = mtile * 128 + mblk2 * 16 + g;
    int col = slab * 32 + kk * 8 + t;
    const float* base = in + (size_t)row * DD + col;
    float4 o;
    o.x = __uint_as_float(f2tf32(base[0]));
    o.y = __uint_as_float(f2tf32(base[8 * DD]));
    o.z = __uint_as_float(f2tf32(base[4]));
    o.w = __uint_as_float(f2tf32(base[8 * DD + 4]));
    *(float4*)(out + (size_t)f4 * 4) = o;
}

__global__ __launch_bounds__(256) void prep_mask(const int* __restrict__ mask)
{
    size_t idx = (size_t)blockIdx.x * 256 + threadIdx.x;   // word index
    const int4* mp = (const int4*)(mask + idx * 32);
    uint32_t bits = 0;
    #pragma unroll
    for (int q = 0; q < 8; q++) {
        int4 m = mp[q];
        bits |= (m.x != 0 ? 1u : 0u) << (q * 4 + 0);
        bits |= (m.y != 0 ? 1u : 0u) << (q * 4 + 1);
        bits |= (m.z != 0 ? 1u : 0u) << (q * 4 + 2);
        bits |= (m.w != 0 ? 1u : 0u) << (q * 4 + 3);
    }
    g_mbits[idx] = bits;
}

// ---------------------------------------------------------------------------
// fused attention smem layout (floats) — 128-row tile, 2 CTAs/SM
#define OFF_PF 8192
#define OFF_KS 16384
#define OFF_VS 20992
#define OFF_SL 25600      // [2][128]
#define OFF_RL 25856      // [128]
#define ATTN_SMEM_FLOATS 25984

__device__ __forceinline__ void load_K_async(float* Ks, const float* Kg, int j0, int tid) {
    #pragma unroll
    for (int i = 0; i < 4; i++) {
        int f = tid + i * 256, r = f >> 4, c = (f & 15) << 2;
        cpa16(saddr(Ks + r * 72 + c), Kg + (size_t)(j0 + r) * 64 + c);
    }
}
__device__ __forceinline__ void load_V_async(float* Vs, const float* Vg, int j0, int tid) {
    #pragma unroll
    for (int i = 0; i < 4; i++) {
        int f = tid + i * 256, r = f >> 4, c = (f & 15) << 2;
        cpa16(saddr(Vs + r * 72 + c), Vg + (size_t)r * SS + j0 + c);
    }
}

// Single pass, 2 syncs per chunk:
//   syncA (top): K_c staged; all warps done PV_{c-1}  -> issue V_c load
//   syncB (mid): Pf staged; all warps done QK_c reads -> issue K_{c+1} load
__global__ __launch_bounds__(256, 2) void fused_attn(float* __restrict__ attn)
{
    extern __shared__ float sm[];
    float* Qf = sm;               // frag-major, 8192
    float* Pf = sm + OFF_PF;      // frag-major, 8192
    float* Ks = sm + OFF_KS;      // [64][72] single buffer
    float* Vs = sm + OFF_VS;      // [64][72] single buffer
    float* SL = sm + OFF_SL;
    float* RL = sm + OFF_RL;

    int bh = blockIdx.y, b = bh >> 4, hh = bh & 15;
    int i0 = blockIdx.x * 128;
    const float* Qg = g_q  + ((size_t)bh * SS) * 64;
    const float* Kg = g_k  + ((size_t)bh * SS) * 64;
    const float* Vg = g_vT + (size_t)bh * DKV * SS;

    int tid = threadIdx.x, lane = tid & 31, wid = tid >> 5;
    int wm = wid & 3, wn = wid >> 2, g = lane >> 2, t = lane & 3;
    int xg = (g >> 1) & 3;

    load_K_async(Ks, Kg, 0, tid);
    load_V_async(Vs, Vg, 0, tid);
    cp_commit();

    // Q tile -> frag-major smem, tf32 bits, (1/8)*log2(e) folded in
    const float QSCALE = 0.1803368801f;
    #pragma unroll
    for (int i = 0; i < 8; i++) {
        int f = tid + i * 256, r = f >> 4, cb = (f & 15) << 2;
        float4 v = *(const float4*)(Qg + (size_t)(i0 + r) * 64 + cb);
        int mblk2 = r >> 4, gg = r & 7, h = (r >> 3) & 1;
        int kk = cb >> 3, vhi = (cb >> 2) & 1, xgg = (gg >> 1) & 3;
        float vv[4] = {v.x, v.y, v.z, v.w};
        #pragma unroll
        for (int j = 0; j < 4; j++) {
            int tp = j ^ xgg;
            Qf[frag_idx(mblk2, kk, gg, tp, h + 2 * vhi)]
                = __uint_as_float(f2tf32(vv[j] * QSCALE));
        }
    }

    int rows[4];
    #pragma unroll
    for (int slot = 0; slot < 4; slot++)
        rows[slot] = wm * 32 + (slot >> 1) * 16 + (slot & 1) * 8 + g;

    float lrun[4] = {0.f, 0.f, 0.f, 0.f};
    float acco[2][4][4] = {};

    for (int c = 0; c < NC; c++) {
        cp_wait<0>();            // K_c staged (c=0: K0+V0)
        __syncthreads();         // syncA: PV_{c-1} readers done with Vs
        if (c > 0) {
            load_V_async(Vs, Vg, c * 64, tid);
            cp_commit();         // V_c loads under mask LDG + QK mma
        }

        uint32_t wbits[4];
        #pragma unroll
        for (int slot = 0; slot < 4; slot++)
            wbits[slot] = g_mbits[((size_t)b * SS + i0 + rows[slot]) * (SS / 32)
                                  + c * 2 + wn];

        float acc[2][4][4] = {};
        mma_frag_pair(Qf, Ks, acc, wm, wn, g, t);

        // epilogue: mask-bit select, exp, streaming attn write, stage Pf
        #pragma unroll
        for (int mf = 0; mf < 2; mf++)
            #pragma unroll
            for (int h = 0; h < 2; h++) {
                int slot = mf * 2 + h;
                int row = rows[slot];
                uint32_t wd = wbits[slot];
                float* arow = attn + ((size_t)(bh * SS + i0 + row)) * SS + c * 64;
                #pragma unroll
                for (int nf = 0; nf < 4; nf++) {
                    int bi = nf * 8 + 2 * t;
                    float p0 = ((wd >> bi) & 1u)
                               ? exp2_fast(acc[mf][nf][h * 2 + 0]) : 0.f;
                    float p1 = ((wd >> (bi + 1)) & 1u)
                               ? exp2_fast(acc[mf][nf][h * 2 + 1]) : 0.f;
                    lrun[slot] += p0 + p1;
                    int jl = wn * 32 + bi;
                    stcs2(arow + jl, p0, p1);
                    int kk = wn * 4 + nf;
                    int t0 = (2 * t) & 3, v0 = t >> 1;
                    Pf[frag_idx(wm * 2 + mf, kk, g, t0 ^ xg, h + 2 * v0)]
                        = __uint_as_float(f2tf32(p0));
                    Pf[frag_idx(wm * 2 + mf, kk, g, (t0 + 1) ^ xg, h + 2 * v0)]
                        = __uint_as_float(f2tf32(p1));
                }
            }

        if (c > 0) cp_wait<0>(); // V_c staged
        __syncthreads();         // syncB: Pf visible; Ks QK reads done
        if (c + 1 < NC) {
            load_K_async(Ks, Kg, (c + 1) * 64, tid);
            cp_commit();         // K_{c+1} loads under PV mma
        }

        mma_frag_pair(Pf, Vs, acco, wm, wn, g, t);
    }

    // reduce L: over t lanes, then across the 2 wn warps
    #pragma unroll
    for (int slot = 0; slot < 4; slot++) {
        float s = lrun[slot];
        s += __shfl_xor_sync(~0u, s, 1);
        s += __shfl_xor_sync(~0u, s, 2);
        lrun[slot] = s;
    }
    __syncthreads();             // last PV done before SL reuse of smem region
    if (t == 0) {
        #pragma unroll
        for (int slot = 0; slot < 4; slot++)
            SL[wn * 128 + rows[slot]] = lrun[slot];
    }
    __syncthreads();
    if (tid < 128) {
        float L = SL[tid] + SL[128 + tid];
        float iL = (L > 0.f) ? 1.f / L : 0.f;
        RL[tid] = iL;
        g_invL[(size_t)bh * SS + i0 + tid] = iL;
    }
    __syncthreads();

    #pragma unroll
    for (int mf = 0; mf < 2; mf++)
        #pragma unroll
        for (int h = 0; h < 2; h++) {
            int slot = mf * 2 + h;
            float iL = RL[rows[slot]];
            int s = i0 + rows[slot];
            #pragma unroll
            for (int nf = 0; nf < 4; nf++) {
                int d = wn * 32 + nf * 8 + 2 * t;
                *(float2*)(g_ao + ((size_t)(b * SS + s)) * (HH * DKV) + hh * 64 + d)
                    = make_float2(acco[mf][nf][h * 2 + 0] * iL,
                                  acco[mf][nf][h * 2 + 1] * iL);
            }
        }
}

// ---------------------------------------------------------------------------
__global__ __launch_bounds__(512) void scale_attn(float* __restrict__ attn)
{
    int row = blockIdx.x;
    float iL = g_invL[row];
    float4* p = (float4*)(attn + (size_t)row * SS);
    float4 v = __ldcs(p + threadIdx.x);
    v.x *= iL; v.y *= iL; v.z *= iL; v.w *= iL;
    __stcs(p + threadIdx.x, v);
}

// ---------------------------------------------------------------------------
// Projection GEMM: C = A @ W + bias. CTA tile 128x128, BK=32, 256 threads,
// warp grid 4m x 2n, warp tile 32x64 (nf=8). cp.async double buffered,
// 2 CTAs/SM.
// ---------------------------------------------------------------------------
#define PROJ_SMEM_FLOATS (2*4608 + 2*5120)   // worst case (AFRAG=false)

template<bool AFRAG>
__device__ __forceinline__ void gemm_body(
    const float* __restrict__ Ap, const float* __restrict__ Wt,
    const float* __restrict__ bias, float* __restrict__ Cplain,
    int mode, float* sm)
{
    constexpr int ASZ = AFRAG ? 4096 : 4608;
    constexpr int LDA = 36;                  // only used when !AFRAG
    const int K = DD, N = DD;
    float* As = sm;                          // 2 x ASZ
    float* Ws = sm + 2 * ASZ;                // 2 x 5120 (stride 40)

    int row0 = blockIdx.y * 128, col0 = blockIdx.x * 128;
    int tid = threadIdx.x, lane = tid & 31, wid = tid >> 5;
    int wm = wid & 3, wn = wid >> 2, g = lane >> 2, t = lane & 3;
    int tp = t ^ ((g >> 1) & 3);

    float acc[2][8][4] = {};

    {
        #pragma unroll
        for (int i = 0; i < 4; i++) {
            int f = tid + i * 256;
            if (AFRAG) {
                cpa16(saddr(As + f * 4),
                      Ap + ((size_t)blockIdx.y * 32 + 0) * 4096 + (size_t)f * 4);
            } else {
                int r = f >> 3, c = (f & 7) << 2;
                cpa16(saddr(As + r * LDA + c), Ap + (size_t)(row0 + r) * K + c);
            }
            int r = f >> 3, c = (f & 7) << 2;
            cpa16(saddr(Ws + r * 40 + c), Wt + (size_t)(col0 + r) * K + c);
        }
        cp_commit();
    }

    for (int s = 0; s < K / 32; s++) {
        if (s + 1 < K / 32) {
            int buf = (s + 1) & 1, k0 = (s + 1) * 32;
            #pragma unroll
            for (int i = 0; i < 4; i++) {
                int f = tid + i * 256;
                if (AFRAG) {
                    cpa16(saddr(As + buf * ASZ + f * 4),
                          Ap + ((size_t)blockIdx.y * 32 + s + 1) * 4096 + (size_t)f * 4);
                } else {
                    int r = f >> 3, c = (f & 7) << 2;
                    cpa16(saddr(As + buf * ASZ + r * LDA + c),
                          Ap + (size_t)(row0 + r) * K + k0 + c);
                }
                int r = f >> 3, c = (f & 7) << 2;
                cpa16(saddr(Ws + buf * 5120 + r * 40 + c),
                      Wt + (size_t)(col0 + r) * K + k0 + c);
            }
        }
        cp_commit();
        cp_wait<1>();
        __syncthreads();

        const float* Ab = As + (s & 1) * ASZ;
        const float* Wb = Ws + (s & 1) * 5120;
        #pragma unroll
        for (int kk = 0; kk < 4; kk++) {
            uint32_t a[2][4];
            #pragma unroll
            for (int mf = 0; mf < 2; mf++) {
                if (AFRAG) {
                    float4 av = *(const float4*)(Ab + frag_idx4(wm * 2 + mf, kk, g, tp, 0));
                    a[mf][0] = __float_as_uint(av.x);
                    a[mf][1] = __float_as_uint(av.y);
                    a[mf][2] = __float_as_uint(av.z);
                    a[mf][3] = __float_as_uint(av.w);
                } else {
                    const float* p = Ab + (wm * 32 + mf * 16 + g) * LDA;
                    a[mf][0] = f2tf32(p[kk * 8 + t]);
                    a[mf][1] = f2tf32(p[8 * LDA + kk * 8 + t]);
                    a[mf][2] = f2tf32(p[kk * 8 + t + 4]);
                    a[mf][3] = f2tf32(p[8 * LDA + kk * 8 + t + 4]);
                }
            }
            #pragma unroll
            for (int nf = 0; nf < 8; nf++) {
                float2 bv = *(const float2*)(Wb + (wn * 64 + nf * 8 + g) * 40
                                             + kk * 8 + 2 * t);
                uint32_t bb[2] = {__float_as_uint(bv.x), __float_as_uint(bv.y)};
                #pragma unroll
                for (int mf = 0; mf < 2; mf++)
                    mma8(acc[mf][nf], a[mf], bb);
            }
        }
        __syncthreads();
    }

    #pragma unroll
    for (int mf = 0; mf < 2; mf++) {
        #pragma unroll
        for (int nf = 0; nf < 8; nf++) {
            int n = col0 + wn * 64 + nf * 8 + 2 * t;
            float b0 = bias[n], b1 = bias[n + 1];
            #pragma unroll
            for (int h = 0; h < 2; h++) {
                int m = row0 + wm * 32 + mf * 16 + g + h * 8;
                float v0 = acc[mf][nf][h * 2 + 0] + b0;
                float v1 = acc[mf][nf][h * 2 + 1] + b1;
                if (mode == 0) {
                    *(float2*)(Cplain + (size_t)m * N + n) = make_float2(v0, v1);
                } else {
                    int b = m >> 11, ss = m & (SS - 1);
                    int hh = n >> 6, d = n & 63;
                    if (mode == 1) {
                        *(float2*)(g_q + ((((size_t)(b * HH + hh)) * SS + ss) << 6) + d)
                            = make_float2(v0, v1);
                    } else if (mode == 2) {
                        size_t base = ((((size_t)(b * HH + hh)) * SS + ss) << 6) + (d & ~7);
                        g_k[base + kperm(d & 7)]       = __uint_as_float(f2tf32(v0));
                        g_k[base + kperm((d & 7) + 1)] = __uint_as_float(f2tf32(v1));
                    } else {
                        int sp = (ss & ~7) | kperm(ss & 7);
                        float* dst = g_vT + ((size_t)(b * HH + hh) * DKV + d) * SS + sp;
                        dst[0]  = __uint_as_float(f2tf32(v0));
                        dst[SS] = __uint_as_float(f2tf32(v1));
                    }
                }
            }
        }
    }
}

__global__ __launch_bounds__(256, 2) void gemm_qkv(
    const float* __restrict__ bq, const float* __restrict__ bk,
    const float* __restrict__ bv)
{
    extern __shared__ float sm[];
    int z = blockIdx.z;
    const float* A    = g_in + (size_t)z * BB * SS * DD;
    const float* Wt   = g_wT + (size_t)z * DD * DD;
    const float* bias = (z == 0) ? bq : (z == 1) ? bk : bv;
    gemm_body<true>(A, Wt, bias, nullptr, z + 1, sm);
}

__global__ __launch_bounds__(256, 2) void gemm_out(
    const float* __restrict__ bo, float* __restrict__ C)
{
    extern __shared__ float sm[];
    gemm_body<false>(g_ao, g_wT + (size_t)3 * DD * DD, bo, C, 0, sm);
}

// ---------------------------------------------------------------------------
extern "C" void kernel_launch(void* const* d_in, const int* in_sizes, int n_in,
                              void* d_out, int out_size)
{
    const float* query = (const float*)d_in[0];
    const float* key   = (const float*)d_in[1];
    const float* value = (const float*)d_in[2];
    const int*   mask  = (const int*)  d_in[3];
    const float* Wq = (const float*)d_in[4];
    const float* bq = (const float*)d_in[5];
    const float* Wk = (const float*)d_in[6];
    const float* bk = (const float*)d_in[7];
    const float* Wv = (const float*)d_in[8];
    const float* bv = (const float*)d_in[9];
    const float* Wo = (const float*)d_in[10];
    const float* bo = (const float*)d_in[11];

    float* out  = (float*)d_out;
    float* attn = out + OUT_OFF;

    static cudaStream_t s2 = nullptr;
    static cudaEvent_t  e0 = nullptr, e1 = nullptr, e2 = nullptr, e3 = nullptr;
    if (s2 == nullptr) {
        cudaStreamCreateWithFlags(&s2, cudaStreamNonBlocking);
        cudaEventCreateWithFlags(&e0, cudaEventDisableTiming);
        cudaEventCreateWithFlags(&e1, cudaEventDisableTiming);
        cudaEventCreateWithFlags(&e2, cudaEventDisableTiming);
        cudaEventCreateWithFlags(&e3, cudaEventDisableTiming);
        cudaFuncSetAttribute(fused_attn, cudaFuncAttributeMaxDynamicSharedMemorySize,
                             ATTN_SMEM_FLOATS * sizeof(float));
        cudaFuncSetAttribute(gemm_qkv, cudaFuncAttributeMaxDynamicSharedMemorySize,
                             PROJ_SMEM_FLOATS * sizeof(float));
        cudaFuncSetAttribute(gemm_out, cudaFuncAttributeMaxDynamicSharedMemorySize,
                             PROJ_SMEM_FLOATS * sizeof(float));
    }

    size_t psm = PROJ_SMEM_FLOATS * sizeof(float);

    // Fork: prep_mask (DRAM-bound) on s2 overlaps the compute-bound chain.
    cudaEventRecord(e0, 0);
    cudaStreamWaitEvent(s2, e0, 0);
    prep_mask<<<1024, 256, 0, s2>>>(mask);
    cudaEventRecord(e1, s2);

    prep_w <<<dim3(32, 32, 4), 256>>>(Wq, Wk, Wv, Wo);
    prep_in<<<dim3(4096, 1, 3), 256>>>(query, key, value);
    gemm_qkv<<<dim3(8, 32, 3), 256, psm>>>(bq, bk, bv);

    cudaStreamWaitEvent(0, e1, 0);              // mask bits ready
    dim3 gAttn(SS / 128, BH);                   // (16, 32)
    fused_attn<<<gAttn, 256, ATTN_SMEM_FLOATS * sizeof(float)>>>(attn);
    cudaEventRecord(e2, 0);

    // Fork: scale_attn (DRAM-bound) on s2 overlaps gemm_out (compute-bound).
    cudaStreamWaitEvent(s2, e2, 0);
    scale_attn<<<BH * SS, 512, 0, s2>>>(attn);
    cudaEventRecord(e3, s2);

    gemm_out<<<dim3(8, 32), 256, psm>>>(bo, out);
    cudaStreamWaitEvent(0, e3, 0);              // join before harness sync
}

// round 17
// speedup vs baseline: 1.0252x; 1.0252x over previous
#include <cuda_runtime.h>
#include <cstdint>

#define BB   2
#define SS   2048
#define DD   1024
#define HH   16
#define DKV  64
#define BH   (BB*HH)
#define NC   (SS/64)      // 32 j-chunks

static const size_t OUT_OFF = (size_t)BB * SS * DD;

__device__ float g_q [(size_t)BH * SS * DKV];          // [bh][s][64] raw fp32
__device__ float g_k [(size_t)BH * SS * DKV];          // [bh][s][64] tf32 bits, d-pair-permuted
__device__ float g_vT[(size_t)BH * DKV * SS];          // [bh][d][s]  tf32 bits, s-pair-permuted
__device__ float g_ao[(size_t)BB * SS * HH * DKV];     // [b][s][h*64+d] raw fp32
__device__ float g_invL[(size_t)BH * SS];              // per-row 1/L
__device__ float g_wT [(size_t)4 * DD * DD];           // [z][n][k] tf32 bits, k-pair-permuted
__device__ float g_in [(size_t)3 * BB * SS * DD];      // [z] slab-frag-major tf32 bits
__device__ uint32_t g_mbits[(size_t)BB * SS * (SS/32)];// packed mask bits

// ---------------------------------------------------------------------------
__device__ __forceinline__ uint32_t f2tf32(float x) {
    uint32_t u;
    asm("cvt.rna.tf32.f32 %0, %1;" : "=r"(u) : "f"(x));
    return u;
}
__device__ __forceinline__ void mma8(float c[4], const uint32_t a[4], const uint32_t b[2]) {
    asm volatile(
        "mma.sync.aligned.m16n8k8.row.col.f32.tf32.tf32.f32 "
        "{%0,%1,%2,%3}, {%4,%5,%6,%7}, {%8,%9}, {%0,%1,%2,%3};\n"
        : "+f"(c[0]), "+f"(c[1]), "+f"(c[2]), "+f"(c[3])
        : "r"(a[0]), "r"(a[1]), "r"(a[2]), "r"(a[3]), "r"(b[0]), "r"(b[1]));
}
__device__ __forceinline__ void cpa16(uint32_t dst, const void* src) {
    asm volatile("cp.async.cg.shared.global [%0], [%1], 16;\n" :: "r"(dst), "l"(src));
}
__device__ __forceinline__ void cp_commit() { asm volatile("cp.async.commit_group;\n"); }
template<int N> __device__ __forceinline__ void cp_wait() {
    asm volatile("cp.async.wait_group %0;\n" :: "n"(N));
}
__device__ __forceinline__ uint32_t saddr(const void* p) {
    return (uint32_t)__cvta_generic_to_shared(p);
}
__device__ __forceinline__ void stcs2(float* p, float x, float y) {
    asm volatile("st.global.cs.v2.f32 [%0], {%1, %2};\n" :: "l"(p), "f"(x), "f"(y) : "memory");
}

// pair permutation within an 8-group: logical k=t and k=t+4 become adjacent.
__device__ __forceinline__ int kperm(int l) { return 2 * (l & 3) + (l >> 2); }

// 2^t on fma/alu pipes (no MUFU). Degree-4 poly, max rel err ~4e-5.
__device__ __forceinline__ float exp2_fast(float t) {
    float kf = t + 12582912.0f;
    int   n  = __float_as_int(kf) - 0x4B400000;
    float r  = t - (kf - 12582912.0f);
    float p  = 0.0096181291f;
    p = fmaf(p, r, 0.0555041087f);
    p = fmaf(p, r, 0.2402265070f);
    p = fmaf(p, r, 0.6931471806f);
    p = fmaf(p, r, 1.0f);
    return p * __int_as_float((n + 127) << 23);
}

// Fragment-major A index, K=64 tiles (fused_attn Q/P): kk in [0,8)
__device__ __forceinline__ int frag_idx(int mblk2, int kk, int g, int tp, int elem) {
    return ((((mblk2 * 8 + kk) * 8) + g) * 4 + tp) * 4 + elem;
}
// Fragment-major A index, BK=32 slabs (projection A): kk in [0,4)
__device__ __forceinline__ int frag_idx4(int mblk2, int kk, int g, int tp, int elem) {
    return ((((mblk2 * 4 + kk) * 8) + g) * 4 + tp) * 4 + elem;
}

// A: frag-major tf32 bits (K=64). B: [64 rows][72] pair-permuted tf32 bits.
__device__ __forceinline__ void mma_frag_pair(
    const float* __restrict__ Af, const float* __restrict__ Bs,
    float acc[2][4][4], int wm, int wn, int g, int t)
{
    int tp = t ^ ((g >> 1) & 3);
    #pragma unroll
    for (int kk = 0; kk < 8; kk++) {
        uint32_t a[2][4];
        #pragma unroll
        for (int mf = 0; mf < 2; mf++) {
            float4 av = *(const float4*)(Af + frag_idx(wm * 2 + mf, kk, g, tp, 0));
            a[mf][0] = __float_as_uint(av.x);
            a[mf][1] = __float_as_uint(av.y);
            a[mf][2] = __float_as_uint(av.z);
            a[mf][3] = __float_as_uint(av.w);
        }
        #pragma unroll
        for (int nf = 0; nf < 4; nf++) {
            float2 bv = *(const float2*)(Bs + (wn * 32 + nf * 8 + g) * 72 + kk * 8 + 2 * t);
            uint32_t bb[2] = {__float_as_uint(bv.x), __float_as_uint(bv.y)};
            #pragma unroll
            for (int mf = 0; mf < 2; mf++)
                mma8(acc[mf][nf], a[mf], bb);
        }
    }
}

// ---------------------------------------------------------------------------
// prep kernels
// ---------------------------------------------------------------------------
__global__ __launch_bounds__(256) void prep_w(
    const float* __restrict__ Wq, const float* __restrict__ Wk,
    const float* __restrict__ Wv, const float* __restrict__ Wo)
{
    __shared__ float tl[32][33];
    int z = blockIdx.z;
    const float* W = (z == 0) ? Wq : (z == 1) ? Wk : (z == 2) ? Wv : Wo;
    float* out = g_wT + (size_t)z * DD * DD;
    int n0 = blockIdx.x * 32, k0 = blockIdx.y * 32;
    int tx = threadIdx.x & 31, ty = threadIdx.x >> 5;   // ty 0..7
    #pragma unroll
    for (int i = 0; i < 4; i++)
        tl[ty + i * 8][tx] = W[(size_t)(k0 + ty + i * 8) * DD + n0 + tx];
    __syncthreads();
    #pragma unroll
    for (int i = 0; i < 4; i++) {
        int n = n0 + ty + i * 8;
        int k = k0 + tx;
        out[(size_t)n * DD + (k & ~7) + kperm(k & 7)]
            = __uint_as_float(f2tf32(tl[tx][ty + i * 8]));
    }
}

// Convert the 3 activation inputs into slab-frag-major tf32 layout.
__global__ __launch_bounds__(256) void prep_in(
    const float* __restrict__ q, const float* __restrict__ k,
    const float* __restrict__ v)
{
    int z = blockIdx.z;
    const float* in = (z == 0) ? q : (z == 1) ? k : v;
    float* out = g_in + (size_t)z * BB * SS * DD;
    int f4 = blockIdx.x * 256 + threadIdx.x;      // 0 .. 1,048,575
    int f4idx = f4 & 1023;
    int slab  = (f4 >> 10) & 31;
    int mtile = f4 >> 15;
    int tp = f4idx & 3, g = (f4idx >> 2) & 7;
    int kk = (f4idx >> 5) & 3, mblk2 = f4idx >> 7;
    int t = tp ^ ((g >> 1) & 3);
    int row = mtile * 128 + mblk2 * 16 + g;
    int col = slab * 32 + kk * 8 + t;
    const float* base = in + (size_t)row * DD + col;
    float4 o;
    o.x = __uint_as_float(f2tf32(base[0]));
    o.y = __uint_as_float(f2tf32(base[8 * DD]));
    o.z = __uint_as_float(f2tf32(base[4]));
    o.w = __uint_as_float(f2tf32(base[8 * DD + 4]));
    *(float4*)(out + (size_t)f4 * 4) = o;
}

__global__ __launch_bounds__(256) void prep_mask(const int* __restrict__ mask)
{
    size_t idx = (size_t)blockIdx.x * 256 + threadIdx.x;   // word index
    const int4* mp = (const int4*)(mask + idx * 32);
    uint32_t bits = 0;
    #pragma unroll
    for (int q = 0; q < 8; q++) {
        int4 m = mp[q];
        bits |= (m.x != 0 ? 1u : 0u) << (q * 4 + 0);
        bits |= (m.y != 0 ? 1u : 0u) << (q * 4 + 1);
        bits |= (m.z != 0 ? 1u : 0u) << (q * 4 + 2);
        bits |= (m.w != 0 ? 1u : 0u) << (q * 4 + 3);
    }
    g_mbits[idx] = bits;
}

// ---------------------------------------------------------------------------
// fused attention smem layout (floats) — 128-row tile, 2 CTAs/SM
#define OFF_PF 8192
#define OFF_KS 16384
#define OFF_VS 20992
#define OFF_SL 25600      // [2][128]
#define OFF_RL 25856      // [128]
#define ATTN_SMEM_FLOATS 25984

__device__ __forceinline__ void load_K_async(float* Ks, const float* Kg, int j0, int tid) {
    #pragma unroll
    for (int i = 0; i < 4; i++) {
        int f = tid + i * 256, r = f >> 4, c = (f & 15) << 2;
        cpa16(saddr(Ks + r * 72 + c), Kg + (size_t)(j0 + r) * 64 + c);
    }
}
__device__ __forceinline__ void load_V_async(float* Vs, const float* Vg, int j0, int tid) {
    #pragma unroll
    for (int i = 0; i < 4; i++) {
        int f = tid + i * 256, r = f >> 4, c = (f & 15) << 2;
        cpa16(saddr(Vs + r * 72 + c), Vg + (size_t)r * SS + j0 + c);
    }
}

// R15 schedule (measured best): 4 syncs/chunk, K/V separate commit groups,
// cp_wait<1> keeps one group in flight across each mma phase.
__global__ __launch_bounds__(256, 2) void fused_attn(float* __restrict__ attn)
{
    extern __shared__ float sm[];
    float* Qf = sm;               // frag-major, 8192
    float* Pf = sm + OFF_PF;      // frag-major, 8192
    float* Ks = sm + OFF_KS;      // [64][72] single buffer
    float* Vs = sm + OFF_VS;      // [64][72] single buffer
    float* SL = sm + OFF_SL;
    float* RL = sm + OFF_RL;

    int bh = blockIdx.y, b = bh >> 4, hh = bh & 15;
    int i0 = blockIdx.x * 128;
    const float* Qg = g_q  + ((size_t)bh * SS) * 64;
    const float* Kg = g_k  + ((size_t)bh * SS) * 64;
    const float* Vg = g_vT + (size_t)bh * DKV * SS;

    int tid = threadIdx.x, lane = tid & 31, wid = tid >> 5;
    int wm = wid & 3, wn = wid >> 2, g = lane >> 2, t = lane & 3;
    int xg = (g >> 1) & 3;

    // Q tile -> frag-major smem, tf32 bits, (1/8)*log2(e) folded in
    const float QSCALE = 0.1803368801f;
    #pragma unroll
    for (int i = 0; i < 8; i++) {
        int f = tid + i * 256, r = f >> 4, cb = (f & 15) << 2;
        float4 v = *(const float4*)(Qg + (size_t)(i0 + r) * 64 + cb);
        int mblk2 = r >> 4, gg = r & 7, h = (r >> 3) & 1;
        int kk = cb >> 3, vhi = (cb >> 2) & 1, xgg = (gg >> 1) & 3;
        float vv[4] = {v.x, v.y, v.z, v.w};
        #pragma unroll
        for (int j = 0; j < 4; j++) {
            int tp = j ^ xgg;
            Qf[frag_idx(mblk2, kk, gg, tp, h + 2 * vhi)]
                = __uint_as_float(f2tf32(vv[j] * QSCALE));
        }
    }

    int rows[4];
    #pragma unroll
    for (int slot = 0; slot < 4; slot++)
        rows[slot] = wm * 32 + (slot >> 1) * 16 + (slot & 1) * 8 + g;

    float lrun[4] = {0.f, 0.f, 0.f, 0.f};
    float acco[2][4][4] = {};

    load_K_async(Ks, Kg, 0, tid);
    cp_commit();
    load_V_async(Vs, Vg, 0, tid);
    cp_commit();

    for (int c = 0; c < NC; c++) {
        cp_wait<1>();            // K_c ready
        __syncthreads();

        uint32_t wbits[4];
        #pragma unroll
        for (int slot = 0; slot < 4; slot++)
            wbits[slot] = g_mbits[((size_t)b * SS + i0 + rows[slot]) * (SS / 32)
                                  + c * 2 + wn];

        float acc[2][4][4] = {};
        mma_frag_pair(Qf, Ks, acc, wm, wn, g, t);
        __syncthreads();         // all QK reads of Ks done
        if (c + 1 < NC) load_K_async(Ks, Kg, (c + 1) * 64, tid);
        cp_commit();             // K_{c+1} loads under epilogue+PV

        #pragma unroll
        for (int mf = 0; mf < 2; mf++)
            #pragma unroll
            for (int h = 0; h < 2; h++) {
                int slot = mf * 2 + h;
                int row = rows[slot];
                uint32_t wd = wbits[slot];
                float* arow = attn + ((size_t)(bh * SS + i0 + row)) * SS + c * 64;
                #pragma unroll
                for (int nf = 0; nf < 4; nf++) {
                    int bi = nf * 8 + 2 * t;
                    float p0 = ((wd >> bi) & 1u)
                               ? exp2_fast(acc[mf][nf][h * 2 + 0]) : 0.f;
                    float p1 = ((wd >> (bi + 1)) & 1u)
                               ? exp2_fast(acc[mf][nf][h * 2 + 1]) : 0.f;
                    lrun[slot] += p0 + p1;
                    int jl = wn * 32 + bi;
                    stcs2(arow + jl, p0, p1);     // streaming: keep L2 for K/V
                    int kk = wn * 4 + nf;
                    int t0 = (2 * t) & 3, v0 = t >> 1;
                    Pf[frag_idx(wm * 2 + mf, kk, g, t0 ^ xg, h + 2 * v0)]
                        = __uint_as_float(f2tf32(p0));
                    Pf[frag_idx(wm * 2 + mf, kk, g, (t0 + 1) ^ xg, h + 2 * v0)]
                        = __uint_as_float(f2tf32(p1));
                }
            }

        cp_wait<1>();            // V_c ready
        __syncthreads();         // Pf visible to all

        mma_frag_pair(Pf, Vs, acco, wm, wn, g, t);
        __syncthreads();         // all PV reads done
        if (c + 1 < NC) load_V_async(Vs, Vg, (c + 1) * 64, tid);
        cp_commit();             // V_{c+1} loads under next QK
    }

    // reduce L: over t lanes, then across the 2 wn warps
    #pragma unroll
    for (int slot = 0; slot < 4; slot++) {
        float s = lrun[slot];
        s += __shfl_xor_sync(~0u, s, 1);
        s += __shfl_xor_sync(~0u, s, 2);
        lrun[slot] = s;
    }
    if (t == 0) {
        #pragma unroll
        for (int slot = 0; slot < 4; slot++)
            SL[wn * 128 + rows[slot]] = lrun[slot];
    }
    __syncthreads();
    if (tid < 128) {
        float L = SL[tid] + SL[128 + tid];
        float iL = (L > 0.f) ? 1.f / L : 0.f;
        RL[tid] = iL;
        g_invL[(size_t)bh * SS + i0 + tid] = iL;
    }
    __syncthreads();

    #pragma unroll
    for (int mf = 0; mf < 2; mf++)
        #pragma unroll
        for (int h = 0; h < 2; h++) {
            int slot = mf * 2 + h;
            float iL = RL[rows[slot]];
            int s = i0 + rows[slot];
            #pragma unroll
            for (int nf = 0; nf < 4; nf++) {
                int d = wn * 32 + nf * 8 + 2 * t;
                *(float2*)(g_ao + ((size_t)(b * SS + s)) * (HH * DKV) + hh * 64 + d)
                    = make_float2(acco[mf][nf][h * 2 + 0] * iL,
                                  acco[mf][nf][h * 2 + 1] * iL);
            }
        }
}

// ---------------------------------------------------------------------------
__global__ __launch_bounds__(512) void scale_attn(float* __restrict__ attn)
{
    int row = blockIdx.x;
    float iL = g_invL[row];
    float4* p = (float4*)(attn + (size_t)row * SS);
    float4 v = __ldcs(p + threadIdx.x);
    v.x *= iL; v.y *= iL; v.z *= iL; v.w *= iL;
    __stcs(p + threadIdx.x, v);
}

// ---------------------------------------------------------------------------
// Projection GEMM: C = A @ W + bias. CTA tile 128x128, BK=32, 256 threads,
// warp grid 4m x 2n, warp tile 32x64 (nf=8). cp.async double buffered,
// 2 CTAs/SM.
// ---------------------------------------------------------------------------
#define PROJ_SMEM_FLOATS (2*4608 + 2*5120)   // worst case (AFRAG=false)

template<bool AFRAG>
__device__ __forceinline__ void gemm_body(
    const float* __restrict__ Ap, const float* __restrict__ Wt,
    const float* __restrict__ bias, float* __restrict__ Cplain,
    int mode, float* sm)
{
    constexpr int ASZ = AFRAG ? 4096 : 4608;
    constexpr int LDA = 36;                  // only used when !AFRAG
    const int K = DD, N = DD;
    float* As = sm;                          // 2 x ASZ
    float* Ws = sm + 2 * ASZ;                // 2 x 5120 (stride 40)

    int row0 = blockIdx.y * 128, col0 = blockIdx.x * 128;
    int tid = threadIdx.x, lane = tid & 31, wid = tid >> 5;
    int wm = wid & 3, wn = wid >> 2, g = lane >> 2, t = lane & 3;
    int tp = t ^ ((g >> 1) & 3);

    float acc[2][8][4] = {};

    {
        #pragma unroll
        for (int i = 0; i < 4; i++) {
            int f = tid + i * 256;
            if (AFRAG) {
                cpa16(saddr(As + f * 4),
                      Ap + ((size_t)blockIdx.y * 32 + 0) * 4096 + (size_t)f * 4);
            } else {
                int r = f >> 3, c = (f & 7) << 2;
                cpa16(saddr(As + r * LDA + c), Ap + (size_t)(row0 + r) * K + c);
            }
            int r = f >> 3, c = (f & 7) << 2;
            cpa16(saddr(Ws + r * 40 + c), Wt + (size_t)(col0 + r) * K + c);
        }
        cp_commit();
    }

    for (int s = 0; s < K / 32; s++) {
        if (s + 1 < K / 32) {
            int buf = (s + 1) & 1, k0 = (s + 1) * 32;
            #pragma unroll
            for (int i = 0; i < 4; i++) {
                int f = tid + i * 256;
                if (AFRAG) {
                    cpa16(saddr(As + buf * ASZ + f * 4),
                          Ap + ((size_t)blockIdx.y * 32 + s + 1) * 4096 + (size_t)f * 4);
                } else {
                    int r = f >> 3, c = (f & 7) << 2;
                    cpa16(saddr(As + buf * ASZ + r * LDA + c),
                          Ap + (size_t)(row0 + r) * K + k0 + c);
                }
                int r = f >> 3, c = (f & 7) << 2;
                cpa16(saddr(Ws + buf * 5120 + r * 40 + c),
                      Wt + (size_t)(col0 + r) * K + k0 + c);
            }
        }
        cp_commit();
        cp_wait<1>();
        __syncthreads();

        const float* Ab = As + (s & 1) * ASZ;
        const float* Wb = Ws + (s & 1) * 5120;
        #pragma unroll
        for (int kk = 0; kk < 4; kk++) {
            uint32_t a[2][4];
            #pragma unroll
            for (int mf = 0; mf < 2; mf++) {
                if (AFRAG) {
                    float4 av = *(const float4*)(Ab + frag_idx4(wm * 2 + mf, kk, g, tp, 0));
                    a[mf][0] = __float_as_uint(av.x);
                    a[mf][1] = __float_as_uint(av.y);
                    a[mf][2] = __float_as_uint(av.z);
                    a[mf][3] = __float_as_uint(av.w);
                } else {
                    const float* p = Ab + (wm * 32 + mf * 16 + g) * LDA;
                    a[mf][0] = f2tf32(p[kk * 8 + t]);
                    a[mf][1] = f2tf32(p[8 * LDA + kk * 8 + t]);
                    a[mf][2] = f2tf32(p[kk * 8 + t + 4]);
                    a[mf][3] = f2tf32(p[8 * LDA + kk * 8 + t + 4]);
                }
            }
            #pragma unroll
            for (int nf = 0; nf < 8; nf++) {
                float2 bv = *(const float2*)(Wb + (wn * 64 + nf * 8 + g) * 40
                                             + kk * 8 + 2 * t);
                uint32_t bb[2] = {__float_as_uint(bv.x), __float_as_uint(bv.y)};
                #pragma unroll
                for (int mf = 0; mf < 2; mf++)
                    mma8(acc[mf][nf], a[mf], bb);
            }
        }
        __syncthreads();
    }

    #pragma unroll
    for (int mf = 0; mf < 2; mf++) {
        #pragma unroll
        for (int nf = 0; nf < 8; nf++) {
            int n = col0 + wn * 64 + nf * 8 + 2 * t;
            float b0 = bias[n], b1 = bias[n + 1];
            #pragma unroll
            for (int h = 0; h < 2; h++) {
                int m = row0 + wm * 32 + mf * 16 + g + h * 8;
                float v0 = acc[mf][nf][h * 2 + 0] + b0;
                float v1 = acc[mf][nf][h * 2 + 1] + b1;
                if (mode == 0) {
                    *(float2*)(Cplain + (size_t)m * N + n) = make_float2(v0, v1);
                } else {
                    int b = m >> 11, ss = m & (SS - 1);
                    int hh = n >> 6, d = n & 63;
                    if (mode == 1) {
                        *(float2*)(g_q + ((((size_t)(b * HH + hh)) * SS + ss) << 6) + d)
                            = make_float2(v0, v1);
                    } else if (mode == 2) {
                        size_t base = ((((size_t)(b * HH + hh)) * SS + ss) << 6) + (d & ~7);
                        g_k[base + kperm(d & 7)]       = __uint_as_float(f2tf32(v0));
                        g_k[base + kperm((d & 7) + 1)] = __uint_as_float(f2tf32(v1));
                    } else {
                        int sp = (ss & ~7) | kperm(ss & 7);
                        float* dst = g_vT + ((size_t)(b * HH + hh) * DKV + d) * SS + sp;
                        dst[0]  = __uint_as_float(f2tf32(v0));
                        dst[SS] = __uint_as_float(f2tf32(v1));
                    }
                }
            }
        }
    }
}

__global__ __launch_bounds__(256, 2) void gemm_qkv(
    const float* __restrict__ bq, const float* __restrict__ bk,
    const float* __restrict__ bv)
{
    extern __shared__ float sm[];
    int z = blockIdx.z;
    const float* A    = g_in + (size_t)z * BB * SS * DD;
    const float* Wt   = g_wT + (size_t)z * DD * DD;
    const float* bias = (z == 0) ? bq : (z == 1) ? bk : bv;
    gemm_body<true>(A, Wt, bias, nullptr, z + 1, sm);
}

__global__ __launch_bounds__(256, 2) void gemm_out(
    const float* __restrict__ bo, float* __restrict__ C)
{
    extern __shared__ float sm[];
    gemm_body<false>(g_ao, g_wT + (size_t)3 * DD * DD, bo, C, 0, sm);
}

// ---------------------------------------------------------------------------
extern "C" void kernel_launch(void* const* d_in, const int* in_sizes, int n_in,
                              void* d_out, int out_size)
{
    const float* query = (const float*)d_in[0];
    const float* key   = (const float*)d_in[1];
    const float* value = (const float*)d_in[2];
    const int*   mask  = (const int*)  d_in[3];
    const float* Wq = (const float*)d_in[4];
    const float* bq = (const float*)d_in[5];
    const float* Wk = (const float*)d_in[6];
    const float* bk = (const float*)d_in[7];
    const float* Wv = (const float*)d_in[8];
    const float* bv = (const float*)d_in[9];
    const float* Wo = (const float*)d_in[10];
    const float* bo = (const float*)d_in[11];

    float* out  = (float*)d_out;
    float* attn = out + OUT_OFF;

    static cudaStream_t s2 = nullptr;
    static cudaEvent_t  e0 = nullptr, e1 = nullptr, e2 = nullptr, e3 = nullptr;
    if (s2 == nullptr) {
        cudaStreamCreateWithFlags(&s2, cudaStreamNonBlocking);
        cudaEventCreateWithFlags(&e0, cudaEventDisableTiming);
        cudaEventCreateWithFlags(&e1, cudaEventDisableTiming);
        cudaEventCreateWithFlags(&e2, cudaEventDisableTiming);
        cudaEventCreateWithFlags(&e3, cudaEventDisableTiming);
        cudaFuncSetAttribute(fused_attn, cudaFuncAttributeMaxDynamicSharedMemorySize,
                             ATTN_SMEM_FLOATS * sizeof(float));
        cudaFuncSetAttribute(gemm_qkv, cudaFuncAttributeMaxDynamicSharedMemorySize,
                             PROJ_SMEM_FLOATS * sizeof(float));
        cudaFuncSetAttribute(gemm_out, cudaFuncAttributeMaxDynamicSharedMemorySize,
                             PROJ_SMEM_FLOATS * sizeof(float));
    }

    size_t psm = PROJ_SMEM_FLOATS * sizeof(float);

    // Fork: prep_mask (DRAM-bound) on s2 overlaps the compute-bound chain.
    cudaEventRecord(e0, 0);
    cudaStreamWaitEvent(s2, e0, 0);
    prep_mask<<<1024, 256, 0, s2>>>(mask);
    cudaEventRecord(e1, s2);

    prep_w <<<dim3(32, 32, 4), 256>>>(Wq, Wk, Wv, Wo);
    prep_in<<<dim3(4096, 1, 3), 256>>>(query, key, value);
    gemm_qkv<<<dim3(8, 32, 3), 256, psm>>>(bq, bk, bv);

    cudaStreamWaitEvent(0, e1, 0);              // mask bits ready
    dim3 gAttn(SS / 128, BH);                   // (16, 32)
    fused_attn<<<gAttn, 256, ATTN_SMEM_FLOATS * sizeof(float)>>>(attn);
    cudaEventRecord(e2, 0);

    // Fork: scale_attn (DRAM-bound) on s2 overlaps gemm_out (compute-bound).
    cudaStreamWaitEvent(s2, e2, 0);
    scale_attn<<<BH * SS, 512, 0, s2>>>(attn);
    cudaEventRecord(e3, s2);

    gemm_out<<<dim3(8, 32), 256, psm>>>(bo, out);
    cudaStreamWaitEvent(0, e3, 0);              // join before harness sync
}